// round 5
// baseline (speedup 1.0000x reference)
#include <cuda_runtime.h>
#include <cuda_bf16.h>

#define NVSEG 29000
#define HWSZ  (1024 * 1024)
#define BATCH 16
#define BHW   (BATCH * HWSZ)
#define NPIX4 (BHW / 4)

// Shared-memory cache for the head of g_rep in output_kernel.
// 13312 * 16B = 212,992 B (~208 KB) — under the 227 KB/CTA dynamic-smem cap.
#define NCACHE 13312
#define OUT_BLOCKS 152
#define OUT_THREADS 1024

// __device__ globals are zero-initialized at module load.
// g_acc[v] = {sum_c0, sum_c1, sum_c2, count}. Invariant: zero at
// kernel_launch entry — replaced_kernel re-zeroes after consuming.
__device__ float4 g_acc[NVSEG];
__device__ float4 g_rep[NVSEG];

// Pass 1 (proven R3 form): 4 px/thread, one float4 RED per pixel.
__global__ __launch_bounds__(256) void accumulate_kernel(
    const float* __restrict__ img, const int* __restrict__ seg)
{
    const long t = (long)blockIdx.x * blockDim.x + threadIdx.x;  // 0 .. NPIX4
    const long p = t << 2;
    const int  b = (int)(t >> 18);          // p >> 20
    const long rem = p & (HWSZ - 1);
    const float* base = img + (long)b * 3 * HWSZ + rem;

    const int4   s  = *(const int4*)(seg + p);
    const float4 c0 = *(const float4*)(base + 0 * HWSZ);
    const float4 c1 = *(const float4*)(base + 1 * HWSZ);
    const float4 c2 = *(const float4*)(base + 2 * HWSZ);

    atomicAdd(&g_acc[s.x], make_float4(c0.x, c1.x, c2.x, 1.0f));
    atomicAdd(&g_acc[s.y], make_float4(c0.y, c1.y, c2.y, 1.0f));
    atomicAdd(&g_acc[s.z], make_float4(c0.z, c1.z, c2.z, 1.0f));
    atomicAdd(&g_acc[s.w], make_float4(c0.w, c1.w, c2.w, 1.0f));
}

// Pass 2: rep[v] = fV[v] - sums[v]/max(cnt,1); reset g_acc[v] = 0.
__global__ __launch_bounds__(256) void replaced_kernel(const float* __restrict__ fV) {
    int v = blockIdx.x * blockDim.x + threadIdx.x;
    if (v >= NVSEG) return;
    float4 a = g_acc[v];
    g_acc[v] = make_float4(0.f, 0.f, 0.f, 0.f);
    float inv = 1.0f / fmaxf(a.w, 1.0f);
    float4 r;
    r.x = fV[3 * v + 0] - a.x * inv;
    r.y = fV[3 * v + 1] - a.y * inv;
    r.z = fV[3 * v + 2] - a.z * inv;
    r.w = 0.f;
    g_rep[v] = r;
}

// Pass 3: persistent (1 CTA/SM, 1024 thr). Head of g_rep cached in smem so
// ~46% of scattered gathers become cheap LDS instead of 32-wavefront LDG.
__global__ __launch_bounds__(OUT_THREADS, 1) void output_kernel(
    const float* __restrict__ img, const int* __restrict__ seg,
    float* __restrict__ out)
{
    extern __shared__ float4 s_rep[];
    // Preload cache (g_rep is L2-hot from replaced_kernel).
    for (int i = threadIdx.x; i < NCACHE; i += OUT_THREADS)
        s_rep[i] = g_rep[i];
    __syncthreads();

    const long stride = (long)gridDim.x * OUT_THREADS;
    for (long t = (long)blockIdx.x * OUT_THREADS + threadIdx.x; t < NPIX4; t += stride) {
        const long p = t << 2;
        const int  b = (int)(t >> 18);
        const long rem = p & (HWSZ - 1);
        const float* base = img + (long)b * 3 * HWSZ + rem;

        const int4 s = *(const int4*)(seg + p);

        const float4 r0 = (s.x < NCACHE) ? s_rep[s.x] : g_rep[s.x];
        const float4 r1 = (s.y < NCACHE) ? s_rep[s.y] : g_rep[s.y];
        const float4 r2 = (s.z < NCACHE) ? s_rep[s.z] : g_rep[s.z];
        const float4 r3 = (s.w < NCACHE) ? s_rep[s.w] : g_rep[s.w];

        const float4 c0 = *(const float4*)(base + 0 * HWSZ);
        const float4 c1 = *(const float4*)(base + 1 * HWSZ);
        const float4 c2 = *(const float4*)(base + 2 * HWSZ);

        float4 o0, o1, o2;
        o0.x = c0.x + r0.x;  o0.y = c1.x + r0.y;  o0.z = c2.x + r0.z;  o0.w = c0.y + r1.x;
        o1.x = c1.y + r1.y;  o1.y = c2.y + r1.z;  o1.z = c0.z + r2.x;  o1.w = c1.z + r2.y;
        o2.x = c2.z + r2.z;  o2.y = c0.w + r3.x;  o2.z = c1.w + r3.y;  o2.w = c2.w + r3.z;

        float4* dst = (float4*)(out + p * 3);   // 12t floats -> 16B aligned
        dst[0] = o0;
        dst[1] = o1;
        dst[2] = o2;
    }
}

extern "C" void kernel_launch(void* const* d_in, const int* in_sizes, int n_in,
                              void* d_out, int out_size)
{
    const float* img = (const float*)d_in[0];
    const int*   seg = (const int*)d_in[1];
    const float* fV  = (const float*)d_in[2];
    float* out = (float*)d_out;

    const int threads = 256;
    const int nvBlocks = (NVSEG + threads - 1) / threads;
    const int pixBlocks = NPIX4 / threads;   // 16384
    const size_t smemBytes = (size_t)NCACHE * sizeof(float4);

    // Attribute set is idempotent and not a stream op (capture-safe).
    cudaFuncSetAttribute(output_kernel,
                         cudaFuncAttributeMaxDynamicSharedMemorySize,
                         (int)smemBytes);

    accumulate_kernel<<<pixBlocks, threads>>>(img, seg);
    replaced_kernel<<<nvBlocks, threads>>>(fV);
    output_kernel<<<OUT_BLOCKS, OUT_THREADS, smemBytes>>>(img, seg, out);
}

// round 6
// speedup vs baseline: 1.2665x; 1.2665x over previous
#include <cuda_runtime.h>
#include <cuda_bf16.h>

#define NVSEG 29000
#define HWSZ  (1024 * 1024)
#define BATCH 16
#define BHW   (BATCH * HWSZ)
#define NPIX4 (BHW / 4)

// __device__ globals are zero-initialized at module load.
// g_acc[v] = {sum_c0, sum_c1, sum_c2, count}. Invariant: zero at
// kernel_launch entry — replaced_kernel re-zeroes after consuming.
__device__ float4 g_acc[NVSEG];
__device__ float4 g_rep[NVSEG];

// Pass 1: 4 px/thread, one float4 RED per pixel.
// launch_bounds(256,8): cap regs at 32 -> 8 CTAs/SM -> full occupancy,
// more independent load/RED chains in flight per SM.
__global__ __launch_bounds__(256, 8) void accumulate_kernel(
    const float* __restrict__ img, const int* __restrict__ seg)
{
    const long t = (long)blockIdx.x * blockDim.x + threadIdx.x;  // 0 .. NPIX4
    const long p = t << 2;
    const int  b = (int)(t >> 18);          // p >> 20
    const long rem = p & (HWSZ - 1);
    const float* base = img + (long)b * 3 * HWSZ + rem;

    const int4   s  = *(const int4*)(seg + p);
    const float4 c0 = *(const float4*)(base + 0 * HWSZ);
    const float4 c1 = *(const float4*)(base + 1 * HWSZ);
    const float4 c2 = *(const float4*)(base + 2 * HWSZ);

    atomicAdd(&g_acc[s.x], make_float4(c0.x, c1.x, c2.x, 1.0f));
    atomicAdd(&g_acc[s.y], make_float4(c0.y, c1.y, c2.y, 1.0f));
    atomicAdd(&g_acc[s.z], make_float4(c0.z, c1.z, c2.z, 1.0f));
    atomicAdd(&g_acc[s.w], make_float4(c0.w, c1.w, c2.w, 1.0f));
}

// Pass 2: rep[v] = fV[v] - sums[v]/max(cnt,1); reset g_acc[v] = 0.
__global__ __launch_bounds__(256) void replaced_kernel(const float* __restrict__ fV) {
    int v = blockIdx.x * blockDim.x + threadIdx.x;
    if (v >= NVSEG) return;
    float4 a = g_acc[v];
    g_acc[v] = make_float4(0.f, 0.f, 0.f, 0.f);
    float inv = 1.0f / fmaxf(a.w, 1.0f);
    float4 r;
    r.x = fV[3 * v + 0] - a.x * inv;
    r.y = fV[3 * v + 1] - a.y * inv;
    r.z = fV[3 * v + 2] - a.z * inv;
    r.w = 0.f;
    g_rep[v] = r;
}

// Pass 3: out[p,c] = pixels[p,c] + rep[seg[p],c]. 4 px/thread, gathers first.
__global__ __launch_bounds__(256, 8) void output_kernel(
    const float* __restrict__ img, const int* __restrict__ seg,
    float* __restrict__ out)
{
    const long t = (long)blockIdx.x * blockDim.x + threadIdx.x;
    const long p = t << 2;
    const int  b = (int)(t >> 18);
    const long rem = p & (HWSZ - 1);
    const float* base = img + (long)b * 3 * HWSZ + rem;

    const int4 s = *(const int4*)(seg + p);

    const float4 r0 = g_rep[s.x];
    const float4 r1 = g_rep[s.y];
    const float4 r2 = g_rep[s.z];
    const float4 r3 = g_rep[s.w];

    const float4 c0 = *(const float4*)(base + 0 * HWSZ);
    const float4 c1 = *(const float4*)(base + 1 * HWSZ);
    const float4 c2 = *(const float4*)(base + 2 * HWSZ);

    float4 o0, o1, o2;
    o0.x = c0.x + r0.x;  o0.y = c1.x + r0.y;  o0.z = c2.x + r0.z;  o0.w = c0.y + r1.x;
    o1.x = c1.y + r1.y;  o1.y = c2.y + r1.z;  o1.z = c0.z + r2.x;  o1.w = c1.z + r2.y;
    o2.x = c2.z + r2.z;  o2.y = c0.w + r3.x;  o2.z = c1.w + r3.y;  o2.w = c2.w + r3.z;

    float4* dst = (float4*)(out + p * 3);   // 12t floats -> 16B aligned
    dst[0] = o0;
    dst[1] = o1;
    dst[2] = o2;
}

extern "C" void kernel_launch(void* const* d_in, const int* in_sizes, int n_in,
                              void* d_out, int out_size)
{
    const float* img = (const float*)d_in[0];
    const int*   seg = (const int*)d_in[1];
    const float* fV  = (const float*)d_in[2];
    float* out = (float*)d_out;

    const int threads = 256;
    const int nvBlocks = (NVSEG + threads - 1) / threads;
    const int pixBlocks = NPIX4 / threads;   // 16384

    accumulate_kernel<<<pixBlocks, threads>>>(img, seg);
    replaced_kernel<<<nvBlocks, threads>>>(fV);
    output_kernel<<<pixBlocks, threads>>>(img, seg, out);
}

// round 7
// speedup vs baseline: 1.3077x; 1.0325x over previous
#include <cuda_runtime.h>
#include <cuda_bf16.h>
#include <cstdint>

#define NVSEG 29000
#define HWSZ  (1024 * 1024)
#define BATCH 16
#define BHW   (BATCH * HWSZ)
#define NPIX4 (BHW / 4)

// smem cache for head of g_rep in output_kernel: 12288 * 16B = 192 KB.
#define NCACHE 12288
#define OUT_BLOCKS 152
#define OUT_THREADS 1024

// __device__ globals are zero-initialized at module load.
// g_acc[v] = {sum_c0, sum_c1, sum_c2, count}. Invariant: zero at
// kernel_launch entry — replaced_kernel re-zeroes after consuming.
__device__ float4 g_acc[NVSEG];
__device__ float4 g_rep[NVSEG];

// Pass 1 (proven R3 form, fastest measured): 4 px/thread, one float4 RED/px.
__global__ __launch_bounds__(256) void accumulate_kernel(
    const float* __restrict__ img, const int* __restrict__ seg)
{
    const long t = (long)blockIdx.x * blockDim.x + threadIdx.x;  // 0 .. NPIX4
    const long p = t << 2;
    const int  b = (int)(t >> 18);          // p >> 20
    const long rem = p & (HWSZ - 1);
    const float* base = img + (long)b * 3 * HWSZ + rem;

    const int4   s  = *(const int4*)(seg + p);
    const float4 c0 = *(const float4*)(base + 0 * HWSZ);
    const float4 c1 = *(const float4*)(base + 1 * HWSZ);
    const float4 c2 = *(const float4*)(base + 2 * HWSZ);

    atomicAdd(&g_acc[s.x], make_float4(c0.x, c1.x, c2.x, 1.0f));
    atomicAdd(&g_acc[s.y], make_float4(c0.y, c1.y, c2.y, 1.0f));
    atomicAdd(&g_acc[s.z], make_float4(c0.z, c1.z, c2.z, 1.0f));
    atomicAdd(&g_acc[s.w], make_float4(c0.w, c1.w, c2.w, 1.0f));
}

// Pass 2: rep[v] = fV[v] - sums[v]/max(cnt,1); reset g_acc[v] = 0.
__global__ __launch_bounds__(256) void replaced_kernel(const float* __restrict__ fV) {
    int v = blockIdx.x * blockDim.x + threadIdx.x;
    if (v >= NVSEG) return;
    float4 a = g_acc[v];
    g_acc[v] = make_float4(0.f, 0.f, 0.f, 0.f);
    float inv = 1.0f / fmaxf(a.w, 1.0f);
    float4 r;
    r.x = fV[3 * v + 0] - a.x * inv;
    r.y = fV[3 * v + 1] - a.y * inv;
    r.z = fV[3 * v + 2] - a.z * inv;
    r.w = 0.f;
    g_rep[v] = r;
}

// Branchless hybrid gather: predicated LDS (cache hit) / LDG (miss) writing
// the same destination regs. No BSSY/BSYNC; predicated-off LDG lanes emit
// no L1tex wavefronts, so the L1tex pipe sees only the ~58% miss lanes while
// the smem crossbar serves hits in parallel.
__device__ __forceinline__ float4 gather_rep(int s, uint32_t smem_base,
                                             const float4* __restrict__ grep)
{
    float4 r;
    uint32_t saddr = smem_base + ((uint32_t)s << 4);
    const float4* gaddr = grep + s;
    asm volatile(
        "{\n\t"
        ".reg .pred p;\n\t"
        "setp.lt.s32 p, %4, %5;\n\t"
        "@p  ld.shared.v4.f32 {%0,%1,%2,%3}, [%6];\n\t"
        "@!p ld.global.nc.v4.f32 {%0,%1,%2,%3}, [%7];\n\t"
        "}"
        : "=f"(r.x), "=f"(r.y), "=f"(r.z), "=f"(r.w)
        : "r"(s), "n"(NCACHE), "r"(saddr), "l"(gaddr));
    return r;
}

// Pass 3: persistent-ish (152 CTAs x 1024 thr, 1 CTA/SM), head of g_rep in smem.
__global__ __launch_bounds__(OUT_THREADS, 1) void output_kernel(
    const float* __restrict__ img, const int* __restrict__ seg,
    float* __restrict__ out)
{
    extern __shared__ float4 s_rep[];
    const uint32_t smem_base = (uint32_t)__cvta_generic_to_shared(s_rep);

    for (int i = threadIdx.x; i < NCACHE; i += OUT_THREADS)
        s_rep[i] = g_rep[i];          // g_rep is L2-hot from replaced_kernel
    __syncthreads();

    const long stride = (long)gridDim.x * OUT_THREADS;
    for (long t = (long)blockIdx.x * OUT_THREADS + threadIdx.x; t < NPIX4; t += stride) {
        const long p = t << 2;
        const int  b = (int)(t >> 18);
        const long rem = p & (HWSZ - 1);
        const float* base = img + (long)b * 3 * HWSZ + rem;

        const int4 s = *(const int4*)(seg + p);

        const float4 r0 = gather_rep(s.x, smem_base, g_rep);
        const float4 r1 = gather_rep(s.y, smem_base, g_rep);
        const float4 r2 = gather_rep(s.z, smem_base, g_rep);
        const float4 r3 = gather_rep(s.w, smem_base, g_rep);

        const float4 c0 = *(const float4*)(base + 0 * HWSZ);
        const float4 c1 = *(const float4*)(base + 1 * HWSZ);
        const float4 c2 = *(const float4*)(base + 2 * HWSZ);

        float4 o0, o1, o2;
        o0.x = c0.x + r0.x;  o0.y = c1.x + r0.y;  o0.z = c2.x + r0.z;  o0.w = c0.y + r1.x;
        o1.x = c1.y + r1.y;  o1.y = c2.y + r1.z;  o1.z = c0.z + r2.x;  o1.w = c1.z + r2.y;
        o2.x = c2.z + r2.z;  o2.y = c0.w + r3.x;  o2.z = c1.w + r3.y;  o2.w = c2.w + r3.z;

        float4* dst = (float4*)(out + p * 3);   // 12t floats -> 16B aligned
        dst[0] = o0;
        dst[1] = o1;
        dst[2] = o2;
    }
}

extern "C" void kernel_launch(void* const* d_in, const int* in_sizes, int n_in,
                              void* d_out, int out_size)
{
    const float* img = (const float*)d_in[0];
    const int*   seg = (const int*)d_in[1];
    const float* fV  = (const float*)d_in[2];
    float* out = (float*)d_out;

    const int threads = 256;
    const int nvBlocks = (NVSEG + threads - 1) / threads;
    const int pixBlocks = NPIX4 / threads;   // 16384
    const size_t smemBytes = (size_t)NCACHE * sizeof(float4);   // 192 KB

    cudaFuncSetAttribute(output_kernel,
                         cudaFuncAttributeMaxDynamicSharedMemorySize,
                         (int)smemBytes);

    accumulate_kernel<<<pixBlocks, threads>>>(img, seg);
    replaced_kernel<<<nvBlocks, threads>>>(fV);
    output_kernel<<<OUT_BLOCKS, OUT_THREADS, smemBytes>>>(img, seg, out);
}

// round 8
// speedup vs baseline: 1.3480x; 1.0308x over previous
#include <cuda_runtime.h>
#include <cuda_bf16.h>

#define NVSEG 29000
#define HWSZ  (1024 * 1024)
#define BATCH 16
#define BHW   (BATCH * HWSZ)

// __device__ globals are zero-initialized at module load.
// g_acc[v] = {sum_c0, sum_c1, sum_c2, count}. Invariant: zero at
// kernel_launch entry — replaced_kernel re-zeroes after consuming.
__device__ float4 g_acc[NVSEG];
__device__ float4 g_rep[NVSEG];

// Pass 1: 2 px/thread (shortest RED burst per thread, max eligible warps),
// one float4 RED per pixel.
__global__ __launch_bounds__(256) void accumulate_kernel(
    const float* __restrict__ img, const int* __restrict__ seg)
{
    const long t = (long)blockIdx.x * blockDim.x + threadIdx.x;  // 0 .. BHW/2
    const long p = t << 1;
    const int  b = (int)(t >> 19);          // p >> 20
    const long rem = p & (HWSZ - 1);
    const float* base = img + (long)b * 3 * HWSZ + rem;

    const int2   s  = *(const int2*)(seg + p);
    const float2 c0 = *(const float2*)(base + 0 * HWSZ);
    const float2 c1 = *(const float2*)(base + 1 * HWSZ);
    const float2 c2 = *(const float2*)(base + 2 * HWSZ);

    atomicAdd(&g_acc[s.x], make_float4(c0.x, c1.x, c2.x, 1.0f));
    atomicAdd(&g_acc[s.y], make_float4(c0.y, c1.y, c2.y, 1.0f));
}

// Pass 2: rep[v] = fV[v] - sums[v]/max(cnt,1); reset g_acc[v] = 0.
__global__ __launch_bounds__(256) void replaced_kernel(const float* __restrict__ fV) {
    int v = blockIdx.x * blockDim.x + threadIdx.x;
    if (v >= NVSEG) return;
    float4 a = g_acc[v];
    g_acc[v] = make_float4(0.f, 0.f, 0.f, 0.f);
    float inv = 1.0f / fmaxf(a.w, 1.0f);
    float4 r;
    r.x = fV[3 * v + 0] - a.x * inv;
    r.y = fV[3 * v + 1] - a.y * inv;
    r.z = fV[3 * v + 2] - a.z * inv;
    r.w = 0.f;
    g_rep[v] = r;
}

// Pass 3 (proven R3 form): 4 px/thread, gathers first, float4 stores.
__global__ __launch_bounds__(256) void output_kernel(
    const float* __restrict__ img, const int* __restrict__ seg,
    float* __restrict__ out)
{
    const long t = (long)blockIdx.x * blockDim.x + threadIdx.x;
    const long p = t << 2;
    const int  b = (int)(t >> 18);
    const long rem = p & (HWSZ - 1);
    const float* base = img + (long)b * 3 * HWSZ + rem;

    const int4 s = *(const int4*)(seg + p);

    const float4 r0 = g_rep[s.x];
    const float4 r1 = g_rep[s.y];
    const float4 r2 = g_rep[s.z];
    const float4 r3 = g_rep[s.w];

    const float4 c0 = *(const float4*)(base + 0 * HWSZ);
    const float4 c1 = *(const float4*)(base + 1 * HWSZ);
    const float4 c2 = *(const float4*)(base + 2 * HWSZ);

    float4 o0, o1, o2;
    o0.x = c0.x + r0.x;  o0.y = c1.x + r0.y;  o0.z = c2.x + r0.z;  o0.w = c0.y + r1.x;
    o1.x = c1.y + r1.y;  o1.y = c2.y + r1.z;  o1.z = c0.z + r2.x;  o1.w = c1.z + r2.y;
    o2.x = c2.z + r2.z;  o2.y = c0.w + r3.x;  o2.z = c1.w + r3.y;  o2.w = c2.w + r3.z;

    float4* dst = (float4*)(out + p * 3);   // 12t floats -> 16B aligned
    dst[0] = o0;
    dst[1] = o1;
    dst[2] = o2;
}

extern "C" void kernel_launch(void* const* d_in, const int* in_sizes, int n_in,
                              void* d_out, int out_size)
{
    const float* img = (const float*)d_in[0];
    const int*   seg = (const int*)d_in[1];
    const float* fV  = (const float*)d_in[2];
    float* out = (float*)d_out;

    const int threads = 256;
    const int nvBlocks = (NVSEG + threads - 1) / threads;
    const int accBlocks = (BHW / 2) / threads;   // 32768
    const int outBlocks = (BHW / 4) / threads;   // 16384

    accumulate_kernel<<<accBlocks, threads>>>(img, seg);
    replaced_kernel<<<nvBlocks, threads>>>(fV);
    output_kernel<<<outBlocks, threads>>>(img, seg, out);
}